// round 12
// baseline (speedup 1.0000x reference)
#include <cuda_runtime.h>
#include <cuda_fp16.h>
#include <mma.h>
#include <math.h>

using namespace nvcuda;

#define BMAX 65536
#define HIS 5
#define KINDS 10

// ---------------------------------------------------------------------------
// Device scratch
// ---------------------------------------------------------------------------
static __device__ __half2 g_af2h[104u * BMAX];
static __device__ __half2 g_af2l[104u * BMAX];
static __device__ float2  g_base2[32u * BMAX];     // 64 scalar rows fp32
static __device__ float   g_score[HIS * BMAX];

// Tables / prepped weights
static __device__ float  g_Wc0[64 * 8];            // (W1c-W1b)[:,0:8]
static __device__ float  g_Tc[10 * 16 * 20 * 4];   // [j][o4][kk] float4
// Transposed split fp16 weights, [k][n] row-major:
static __device__ __half g_w1th[208 * 128];
static __device__ __half g_w1tl[208 * 128];
static __device__ __half g_w2th[128 * 64];
static __device__ __half g_w2tl[128 * 64];
static __device__ __half g_w3th[64 * 32];
static __device__ __half g_w3tl[64 * 32];
// ActUnit: Wa = W1a+W1b transposed [k=96(pad)][n=64]; act_w2 transposed [64][32]
static __device__ __half g_wa1th[96 * 64];
static __device__ __half g_wa1tl[96 * 64];
static __device__ __half g_aw2th[64 * 32];
static __device__ __half g_aw2tl[64 * 32];

__device__ __forceinline__ float4 ldg4(const float* p) {
    return __ldg((const float4*)p);
}

__device__ __forceinline__ void st_feat(int B, int b, int rp, float x, float y) {
    __half hx = __float2half_rn(x), hy = __float2half_rn(y);
    float lx = x - __half2float(hx), ly = y - __half2float(hy);
    g_af2h[(size_t)rp * (size_t)B + (size_t)b] = __halves2half2(hx, hy);
    g_af2l[(size_t)rp * (size_t)B + (size_t)b] =
        __halves2half2(__float2half_rn(lx), __float2half_rn(ly));
}

__device__ __forceinline__ void st8(int B, int b, int rp, float4 v0, float4 v1) {
    st_feat(B, b, rp + 0, v0.x, v0.y);
    st_feat(B, b, rp + 1, v0.z, v0.w);
    st_feat(B, b, rp + 2, v1.x, v1.y);
    st_feat(B, b, rp + 3, v1.z, v1.w);
}

// ---------------------------------------------------------------------------
// prep
// ---------------------------------------------------------------------------
extern "C" __global__ void prep_tables(const float* __restrict__ act_w1,
                                       const float* __restrict__ act_w2,
                                       const float* __restrict__ mlp_w1,
                                       const float* __restrict__ mlp_w2,
                                       const float* __restrict__ mlp_w3,
                                       const float* __restrict__ kind_emb)
{
    int i = blockIdx.x * blockDim.x + threadIdx.x;
    if (i < 512) {
        int o = i >> 3, d = i & 7;
        const float* r = act_w1 + o * 264;
        g_Wc0[o * 8 + d] = r[176 + d] - r[88 + d];
        return;
    }
    i -= 512;
    if (i < 12800) {
        int f = i & 3; int r1 = i >> 2;
        int kk = r1 % 20; r1 /= 20;
        int o4 = r1 % 16; int j = r1 / 16;
        int o = 4 * o4 + f;
        float v = 0.f;
        if (kk != 0) {
            const float* r = act_w1 + o * 264 + 8 * (j + 1);
            const float* e = kind_emb + kk * 8;
            #pragma unroll
            for (int d = 0; d < 8; d++)
                v += (r[176 + d] - r[88 + d]) * e[d];
        }
        g_Tc[i] = v;
        return;
    }
    i -= 12800;
    if (i < 26624) {                    // w1t: [k=208][n=128]
        int k = i >> 7, n = i & 127;
        float w = mlp_w1[n * 208 + k];
        __half h = __float2half_rn(w);
        g_w1th[i] = h;
        g_w1tl[i] = __float2half_rn(w - __half2float(h));
        return;
    }
    i -= 26624;
    if (i < 8192) {                     // w2t: [k=128][n=64]
        int k = i >> 6, n = i & 63;
        float w = mlp_w2[n * 128 + k];
        __half h = __float2half_rn(w);
        g_w2th[i] = h;
        g_w2tl[i] = __float2half_rn(w - __half2float(h));
        return;
    }
    i -= 8192;
    if (i < 2048) {                     // w3t: [k=64][n=32]
        int k = i >> 5, n = i & 31;
        float w = mlp_w3[n * 64 + k];
        __half h = __float2half_rn(w);
        g_w3th[i] = h;
        g_w3tl[i] = __float2half_rn(w - __half2float(h));
        return;
    }
    i -= 2048;
    if (i < 6144) {                     // wa1t: [k=96][n=64], k>=88 zero
        int k = i >> 6, n = i & 63;
        float w = 0.f;
        if (k < 88) {
            const float* r = act_w1 + n * 264;
            w = r[k] + r[88 + k];
        }
        __half h = __float2half_rn(w);
        g_wa1th[i] = h;
        g_wa1tl[i] = __float2half_rn(w - __half2float(h));
        return;
    }
    i -= 6144;
    if (i < 2048) {                     // aw2t: [k=64][n=32]
        int k = i >> 5, n = i & 31;
        float w = act_w2[n * 64 + k];
        __half h = __float2half_rn(w);
        g_aw2th[i] = h;
        g_aw2tl[i] = __float2half_rn(w - __half2float(h));
    }
}

// ---------------------------------------------------------------------------
// k0: gathers -> split fp16 all_feat rows 0..119, base -> g_base2 (fp32).
// ---------------------------------------------------------------------------
extern "C" __global__ void __launch_bounds__(128, 4)
k0_feat(const int* __restrict__ userid, const int* __restrict__ itemid,
        const int* __restrict__ user_age, const int* __restrict__ gender,
        const int* __restrict__ user_occ, const int* __restrict__ item_kind,
        const float* __restrict__ user_emb, const float* __restrict__ item_emb,
        const float* __restrict__ age_emb, const float* __restrict__ gender_emb,
        const float* __restrict__ occ_emb, const float* __restrict__ kind_emb,
        const float* __restrict__ act_b1, int B)
{
    __shared__ float sWc0[64 * 8];
    for (int idx = threadIdx.x; idx < 512; idx += blockDim.x) sWc0[idx] = g_Wc0[idx];
    __syncthreads();

    int b = blockIdx.x * blockDim.x + threadIdx.x;
    if (b >= B) return;
    size_t sB = (size_t)B;

    float4 iv0, iv1;
    {
        const float* p = user_emb + (size_t)userid[b] * 8;
        st8(B, b, 0, ldg4(p), ldg4(p + 4));
        p = item_emb + (size_t)itemid[b] * 8;
        iv0 = ldg4(p); iv1 = ldg4(p + 4);
        st8(B, b, 4, iv0, iv1);
        p = age_emb + (size_t)user_age[b] * 8;
        st8(B, b, 8, ldg4(p), ldg4(p + 4));
        p = gender_emb + (size_t)gender[b] * 8;
        st8(B, b, 12, ldg4(p), ldg4(p + 4));
        p = occ_emb + (size_t)user_occ[b] * 8;
        st8(B, b, 16, ldg4(p), ldg4(p + 4));
    }

    float acc[64];
    #pragma unroll
    for (int o = 0; o < 64; o++) acc[o] = __ldg(act_b1 + o);

    #pragma unroll
    for (int o = 0; o < 64; o++) {
        float4 w0 = *(const float4*)(sWc0 + o * 8);
        float4 w1 = *(const float4*)(sWc0 + o * 8 + 4);
        acc[o] += w0.x*iv0.x + w0.y*iv0.y + w0.z*iv0.z + w0.w*iv0.w
                + w1.x*iv1.x + w1.y*iv1.y + w1.z*iv1.z + w1.w*iv1.w;
    }

    #pragma unroll 1
    for (int j = 0; j < 10; j++) {
        int kk = item_kind[b * KINDS + j];
        const float* p = kind_emb + (size_t)kk * 8;
        float4 v0 = ldg4(p), v1 = ldg4(p + 4);
        if (kk == 0) { v0 = make_float4(0.f,0.f,0.f,0.f); v1 = v0; }
        st8(B, b, 20 + 4 * j, v0, v1);
        const float4* t = (const float4*)g_Tc + (size_t)(j * 16) * 20 + kk;
        #pragma unroll
        for (int o4 = 0; o4 < 16; o4++) {
            float4 v = __ldg(t + o4 * 20);
            acc[4*o4+0] += v.x; acc[4*o4+1] += v.y;
            acc[4*o4+2] += v.z; acc[4*o4+3] += v.w;
        }
    }

    float2* bp = g_base2 + (size_t)b;
    #pragma unroll
    for (int o = 0; o < 32; o++)
        bp[(size_t)o * sB] = make_float2(acc[2*o], acc[2*o + 1]);
}

// ---------------------------------------------------------------------------
// t1_score: ActUnit via split-fp16 wmma. 128 (b,s) rows / block, 512 threads.
// ---------------------------------------------------------------------------
#define T1_SMEM 122368

extern "C" __global__ void __launch_bounds__(512, 1)
t1_score(const int* __restrict__ his_id, const int* __restrict__ his_kind,
         const float* __restrict__ item_emb, const float* __restrict__ kind_emb,
         const float* __restrict__ act_b2, const float* __restrict__ act_w3,
         const float* __restrict__ act_b3, int B)
{
    extern __shared__ char smem[];
    __half* sAH  = (__half*)(smem);            // [96][136]
    __half* sAL  = (__half*)(smem + 26112);
    __half* sA2H = (__half*)(smem + 52224);    // [128][72]
    __half* sA2L = (__half*)(smem + 70656);
    float*  sH2  = (float*)(smem + 89088);     // [128][33]
    float*  sScr = (float*)(smem + 105984);    // [16][256]

    int tid = threadIdx.x;
    int w = tid >> 5, lane = tid & 31;
    int mr = w >> 1, nh = w & 1;
    int m0w = mr * 16;
    int m0g = blockIdx.x * 128;
    int NG = 5 * B;
    float* scr = sScr + w * 256;

    typedef wmma::fragment<wmma::matrix_a, 16,16,16, __half, wmma::col_major> FragAc;
    typedef wmma::fragment<wmma::matrix_a, 16,16,16, __half, wmma::row_major> FragAr;
    typedef wmma::fragment<wmma::matrix_b, 16,16,16, __half, wmma::row_major> FragB;
    typedef wmma::fragment<wmma::accumulator, 16,16,16, float> FragC;

    // zero pad rows k=88..95
    for (int i = tid; i < 1088; i += 512) {
        sAH[11968 + i] = __float2half_rn(0.f);
        sAL[11968 + i] = __float2half_rn(0.f);
    }

    // gather features: 4 threads per row, chunks j = q, q+4, q+8
    {
        int r = tid >> 2, q = tid & 3;
        int g = m0g + r;
        if (g >= NG) g = NG - 1;
        int hid = __ldg(his_id + g);
        #pragma unroll
        for (int jj = 0; jj < 3; jj++) {
            int j = q + jj * 4;
            if (j >= 11) break;
            const float* p;
            float mk = 1.f;
            if (j == 0) {
                p = item_emb + (size_t)hid * 8;
            } else {
                int kk = __ldg(his_kind + (size_t)g * KINDS + (j - 1));
                p = kind_emb + (size_t)kk * 8;
                mk = (kk != 0) ? 1.f : 0.f;
            }
            float4 v0 = ldg4(p), v1 = ldg4(p + 4);
            float vv[8] = {v0.x*mk, v0.y*mk, v0.z*mk, v0.w*mk,
                           v1.x*mk, v1.y*mk, v1.z*mk, v1.w*mk};
            #pragma unroll
            for (int d = 0; d < 8; d++) {
                float x = vv[d];
                __half h = __float2half_rn(x);
                sAH[(8*j + d) * 136 + r] = h;
                sAL[(8*j + d) * 136 + r] = __float2half_rn(x - __half2float(h));
            }
        }
    }
    __syncthreads();

    // ===== Layer 1: [128x96] @ [96x64], base added in epilogue =====
    FragC acc[2];
    #pragma unroll
    for (int c = 0; c < 2; c++) wmma::fill_fragment(acc[c], 0.0f);
    int n0base = nh * 32;

    #pragma unroll 1
    for (int t = 0; t < 6; t++) {
        FragAc ah, al;
        wmma::load_matrix_sync(ah, sAH + (16*t)*136 + m0w, 136);
        wmma::load_matrix_sync(al, sAL + (16*t)*136 + m0w, 136);
        #pragma unroll
        for (int c = 0; c < 2; c++) {
            FragB bh, bl;
            wmma::load_matrix_sync(bh, g_wa1th + (16*t)*64 + n0base + 16*c, 64);
            wmma::load_matrix_sync(bl, g_wa1tl + (16*t)*64 + n0base + 16*c, 64);
            wmma::mma_sync(acc[c], ah, bh, acc[c]);
            wmma::mma_sync(acc[c], ah, bl, acc[c]);
            wmma::mma_sync(acc[c], al, bh, acc[c]);
        }
    }

    #pragma unroll 1
    for (int c = 0; c < 2; c++) {
        __syncwarp();
        wmma::store_matrix_sync(scr, acc[c], 16, wmma::mem_row_major);
        __syncwarp();
        int n0 = n0base + 16 * c;
        #pragma unroll
        for (int i = 0; i < 8; i++) {
            int idx = i * 32 + lane;
            int r = idx >> 4, cc = idx & 15;
            int m = m0w + r, n = n0 + cc;
            int g2 = m0g + m;
            if (g2 >= NG) g2 = NG - 1;
            int b = g2 / 5;
            float2 bb = __ldg(&g_base2[(size_t)(n >> 1) * (size_t)B + (size_t)b]);
            float v = scr[idx] + ((n & 1) ? bb.y : bb.x);
            v = fmaxf(v, 0.f);
            __half h = __float2half_rn(v);
            sA2H[m * 72 + n] = h;
            sA2L[m * 72 + n] = __float2half_rn(v - __half2float(h));
        }
    }
    __syncthreads();

    // ===== Layer 2: [128x64] @ [64x32] =====
    FragC acc2;
    wmma::fill_fragment(acc2, 0.0f);
    int n03 = nh * 16;

    #pragma unroll 1
    for (int t = 0; t < 4; t++) {
        FragAr ah, al;
        wmma::load_matrix_sync(ah, sA2H + m0w * 72 + 16 * t, 72);
        wmma::load_matrix_sync(al, sA2L + m0w * 72 + 16 * t, 72);
        FragB bh, bl;
        wmma::load_matrix_sync(bh, g_aw2th + (16*t)*32 + n03, 32);
        wmma::load_matrix_sync(bl, g_aw2tl + (16*t)*32 + n03, 32);
        wmma::mma_sync(acc2, ah, bh, acc2);
        wmma::mma_sync(acc2, ah, bl, acc2);
        wmma::mma_sync(acc2, al, bh, acc2);
    }
    __syncwarp();
    wmma::store_matrix_sync(scr, acc2, 16, wmma::mem_row_major);
    __syncwarp();
    #pragma unroll
    for (int i = 0; i < 8; i++) {
        int idx = i * 32 + lane;
        int r = idx >> 4, cc = idx & 15;
        int m = m0w + r, n = n03 + cc;
        float v = scr[idx] + __ldg(act_b2 + n);
        sH2[m * 33 + n] = fmaxf(v, 0.f);
    }
    __syncthreads();

    // ===== Layer 3: 32 -> 1 score =====
    if (tid < 128) {
        int m = tid;
        int g2 = m0g + m;
        if (g2 < NG) {
            float sc = __ldg(act_b3);
            #pragma unroll
            for (int o = 0; o < 32; o++)
                sc += __ldg(act_w3 + o) * sH2[m * 33 + o];
            int b = g2 / 5, s = g2 - 5 * b;
            g_score[(size_t)s * (size_t)B + (size_t)b] = sc;
        }
    }
}

// ---------------------------------------------------------------------------
// k2: his_pool -> split fp16 rows 120..207 (rowpairs 60..103).
// ---------------------------------------------------------------------------
extern "C" __global__ void __launch_bounds__(128, 4)
k2_pool(const int* __restrict__ his_id, const int* __restrict__ his_kind,
        const float* __restrict__ item_emb, const float* __restrict__ kind_emb,
        int B)
{
    int b = blockIdx.x * blockDim.x + threadIdx.x;
    if (b >= B) return;
    size_t sB = (size_t)B;

    float poolL[88];
    #pragma unroll
    for (int d = 0; d < 88; d++) poolL[d] = 0.f;

    #pragma unroll 1
    for (int s = 0; s < HIS; s++) {
        float sc = g_score[(size_t)s * sB + (size_t)b];
        int hid = his_id[b * HIS + s];
        {
            const float* p = item_emb + (size_t)hid * 8;
            float4 v0 = ldg4(p), v1 = ldg4(p + 4);
            poolL[0] += v0.x*v0.x*sc; poolL[1] += v0.y*v0.y*sc;
            poolL[2] += v0.z*v0.z*sc; poolL[3] += v0.w*v0.w*sc;
            poolL[4] += v1.x*v1.x*sc; poolL[5] += v1.y*v1.y*sc;
            poolL[6] += v1.z*v1.z*sc; poolL[7] += v1.w*v1.w*sc;
        }
        #pragma unroll
        for (int j = 0; j < 10; j++) {
            int kk = his_kind[(b * HIS + s) * KINDS + j];
            const float* p = kind_emb + (size_t)kk * 8;
            float4 v0 = ldg4(p), v1 = ldg4(p + 4);
            float fm = (kk != 0) ? sc : 0.f;
            int pp = 8 + j * 8;
            poolL[pp+0] += v0.x*v0.x*fm; poolL[pp+1] += v0.y*v0.y*fm;
            poolL[pp+2] += v0.z*v0.z*fm; poolL[pp+3] += v0.w*v0.w*fm;
            poolL[pp+4] += v1.x*v1.x*fm; poolL[pp+5] += v1.y*v1.y*fm;
            poolL[pp+6] += v1.z*v1.z*fm; poolL[pp+7] += v1.w*v1.w*fm;
        }
    }
    #pragma unroll 1
    for (int d = 0; d < 44; d++)
        st_feat(B, b, 60 + d, poolL[2*d], poolL[2*d + 1]);
}

// ---------------------------------------------------------------------------
// t2_mlp: fused 208->128->64->32->1 + sigmoid via split-fp16 wmma. (R11)
// ---------------------------------------------------------------------------
#define T2_SMEM 157184

extern "C" __global__ void __launch_bounds__(512, 1)
t2_mlp(const float* __restrict__ mlp_b1, const float* __restrict__ mlp_b2,
       const float* __restrict__ mlp_b3, const float* __restrict__ mlp_w4,
       const float* __restrict__ mlp_b4, float* __restrict__ out, int B)
{
    extern __shared__ char smem[];
    __half* sAkH = (__half*)(smem + 0);        // [16][136]
    __half* sAkL = (__half*)(smem + 4352);
    __half* sBkH = (__half*)(smem + 8704);     // [16][136]
    __half* sBkL = (__half*)(smem + 13056);
    __half* sA2H = (__half*)(smem + 17408);    // [128][136]
    __half* sA2L = (__half*)(smem + 52224);
    __half* sA3H = (__half*)(smem + 87040);    // [128][72]
    __half* sA3L = (__half*)(smem + 105472);
    float*  sScr = (float*)(smem + 123904);    // [16][256]
    float*  sH3  = (float*)(smem + 140288);    // [128][33]

    int tid = threadIdx.x;
    int w = tid >> 5, lane = tid & 31;
    int m0 = blockIdx.x * 128;
    int mr = w >> 1;
    int m0w = mr * 16;
    float* scr = sScr + w * 256;

    typedef wmma::fragment<wmma::matrix_a, 16,16,16, __half, wmma::col_major> FragAc;
    typedef wmma::fragment<wmma::matrix_a, 16,16,16, __half, wmma::row_major> FragAr;
    typedef wmma::fragment<wmma::matrix_b, 16,16,16, __half, wmma::row_major> FragB;
    typedef wmma::fragment<wmma::accumulator, 16,16,16, float> FragC;

    FragC acc[4];
    #pragma unroll
    for (int c = 0; c < 4; c++) wmma::fill_fragment(acc[c], 0.0f);
    int nb1 = (w & 1) * 4;

    #pragma unroll 1
    for (int t = 0; t < 13; t++) {
        __syncthreads();
        #pragma unroll
        for (int i = tid; i < 1024; i += 512) {
            int j = i >> 7, m = i & 127;
            size_t src = (size_t)(8 * t + j) * (size_t)B + (size_t)(m0 + m);
            __half2 vh = g_af2h[src];
            __half2 vl = g_af2l[src];
            sAkH[(2*j) * 136 + m]     = __low2half(vh);
            sAkH[(2*j + 1) * 136 + m] = __high2half(vh);
            sAkL[(2*j) * 136 + m]     = __low2half(vl);
            sAkL[(2*j + 1) * 136 + m] = __high2half(vl);
        }
        #pragma unroll
        for (int i = tid; i < 1024; i += 512) {
            int kk = i >> 6, c2 = i & 63;
            *(__half2*)&sBkH[kk * 136 + 2 * c2] =
                ((const __half2*)g_w1th)[(16 * t + kk) * 64 + c2];
            *(__half2*)&sBkL[kk * 136 + 2 * c2] =
                ((const __half2*)g_w1tl)[(16 * t + kk) * 64 + c2];
        }
        __syncthreads();

        FragAc ah, al;
        wmma::load_matrix_sync(ah, sAkH + m0w, 136);
        wmma::load_matrix_sync(al, sAkL + m0w, 136);
        #pragma unroll
        for (int c = 0; c < 4; c++) {
            int n0 = (nb1 + c) * 16;
            FragB bh, bl;
            wmma::load_matrix_sync(bh, sBkH + n0, 136);
            wmma::load_matrix_sync(bl, sBkL + n0, 136);
            wmma::mma_sync(acc[c], ah, bh, acc[c]);
            wmma::mma_sync(acc[c], ah, bl, acc[c]);
            wmma::mma_sync(acc[c], al, bh, acc[c]);
        }
    }
    #pragma unroll 1
    for (int c = 0; c < 4; c++) {
        __syncwarp();
        wmma::store_matrix_sync(scr, acc[c], 16, wmma::mem_row_major);
        __syncwarp();
        int n0 = (nb1 + c) * 16;
        #pragma unroll
        for (int i = 0; i < 8; i++) {
            int idx = i * 32 + lane;
            int r = idx >> 4, cc = idx & 15;
            int n = n0 + cc, m = m0w + r;
            float v = scr[idx] + __ldg(mlp_b1 + n);
            v = fmaxf(v, 0.f);
            __half hv = __float2half_rn(v);
            sA2H[m * 136 + n] = hv;
            sA2L[m * 136 + n] = __float2half_rn(v - __half2float(hv));
        }
    }
    __syncthreads();

    FragC acc2[2];
    #pragma unroll
    for (int c = 0; c < 2; c++) wmma::fill_fragment(acc2[c], 0.0f);
    int nb2 = (w & 1) * 2;

    #pragma unroll 1
    for (int t = 0; t < 8; t++) {
        __syncthreads();
        if (tid < 512) {
            int kk = tid >> 5, c2 = tid & 31;
            *(__half2*)&sBkH[kk * 136 + 2 * c2] =
                ((const __half2*)g_w2th)[(16 * t + kk) * 32 + c2];
            *(__half2*)&sBkL[kk * 136 + 2 * c2] =
                ((const __half2*)g_w2tl)[(16 * t + kk) * 32 + c2];
        }
        __syncthreads();

        FragAr ah, al;
        wmma::load_matrix_sync(ah, sA2H + m0w * 136 + 16 * t, 136);
        wmma::load_matrix_sync(al, sA2L + m0w * 136 + 16 * t, 136);
        #pragma unroll
        for (int c = 0; c < 2; c++) {
            int n0 = (nb2 + c) * 16;
            FragB bh, bl;
            wmma::load_matrix_sync(bh, sBkH + n0, 136);
            wmma::load_matrix_sync(bl, sBkL + n0, 136);
            wmma::mma_sync(acc2[c], ah, bh, acc2[c]);
            wmma::mma_sync(acc2[c], ah, bl, acc2[c]);
            wmma::mma_sync(acc2[c], al, bh, acc2[c]);
        }
    }
    #pragma unroll 1
    for (int c = 0; c < 2; c++) {
        __syncwarp();
        wmma::store_matrix_sync(scr, acc2[c], 16, wmma::mem_row_major);
        __syncwarp();
        int n0 = (nb2 + c) * 16;
        #pragma unroll
        for (int i = 0; i < 8; i++) {
            int idx = i * 32 + lane;
            int r = idx >> 4, cc = idx & 15;
            int n = n0 + cc, m = m0w + r;
            float v = scr[idx] + __ldg(mlp_b2 + n);
            v = fmaxf(v, 0.f);
            __half hv = __float2half_rn(v);
            sA3H[m * 72 + n] = hv;
            sA3L[m * 72 + n] = __float2half_rn(v - __half2float(hv));
        }
    }
    __syncthreads();

    FragC acc3;
    wmma::fill_fragment(acc3, 0.0f);
    int n03 = (w & 1) * 16;

    #pragma unroll 1
    for (int t = 0; t < 4; t++) {
        __syncthreads();
        if (tid < 256) {
            int kk = tid >> 4, c2 = tid & 15;
            *(__half2*)&sBkH[kk * 136 + 2 * c2] =
                ((const __half2*)g_w3th)[(16 * t + kk) * 16 + c2];
            *(__half2*)&sBkL[kk * 136 + 2 * c2] =
                ((const __half2*)g_w3tl)[(16 * t + kk) * 16 + c2];
        }
        __syncthreads();

        FragAr ah, al;
        wmma::load_matrix_sync(ah, sA3H + m0w * 72 + 16 * t, 72);
        wmma::load_matrix_sync(al, sA3L + m0w * 72 + 16 * t, 72);
        FragB bh, bl;
        wmma::load_matrix_sync(bh, sBkH + n03, 136);
        wmma::load_matrix_sync(bl, sBkL + n03, 136);
        wmma::mma_sync(acc3, ah, bh, acc3);
        wmma::mma_sync(acc3, ah, bl, acc3);
        wmma::mma_sync(acc3, al, bh, acc3);
    }
    __syncwarp();
    wmma::store_matrix_sync(scr, acc3, 16, wmma::mem_row_major);
    __syncwarp();
    #pragma unroll
    for (int i = 0; i < 8; i++) {
        int idx = i * 32 + lane;
        int r = idx >> 4, cc = idx & 15;
        int n = n03 + cc, m = m0w + r;
        float v = scr[idx] + __ldg(mlp_b3 + n);
        sH3[m * 33 + n] = fmaxf(v, 0.f);
    }
    __syncthreads();

    if (tid < 128) {
        int m = tid;
        float logit = __ldg(mlp_b4);
        #pragma unroll
        for (int o = 0; o < 32; o++)
            logit += __ldg(mlp_w4 + o) * sH3[m * 33 + o];
        out[m0 + m] = 1.f / (1.f + expf(-logit));
    }
}

// ---------------------------------------------------------------------------
extern "C" void kernel_launch(void* const* d_in, const int* in_sizes, int n_in,
                              void* d_out, int out_size)
{
    const int*   userid   = (const int*)d_in[0];
    const int*   itemid   = (const int*)d_in[1];
    const int*   user_age = (const int*)d_in[2];
    const int*   gender   = (const int*)d_in[3];
    const int*   user_occ = (const int*)d_in[4];
    const int*   item_kind= (const int*)d_in[5];
    const int*   his_id   = (const int*)d_in[6];
    const int*   his_kind = (const int*)d_in[7];
    const float* user_emb = (const float*)d_in[8];
    const float* item_emb = (const float*)d_in[9];
    const float* age_emb  = (const float*)d_in[10];
    const float* gen_emb  = (const float*)d_in[11];
    const float* occ_emb  = (const float*)d_in[12];
    const float* kind_emb = (const float*)d_in[13];
    const float* act_w1 = (const float*)d_in[14];
    const float* act_b1 = (const float*)d_in[15];
    const float* act_w2 = (const float*)d_in[16];
    const float* act_b2 = (const float*)d_in[17];
    const float* act_w3 = (const float*)d_in[18];
    const float* act_b3 = (const float*)d_in[19];
    const float* mlp_w1 = (const float*)d_in[20];
    const float* mlp_b1 = (const float*)d_in[21];
    const float* mlp_w2 = (const float*)d_in[22];
    const float* mlp_b2 = (const float*)d_in[23];
    const float* mlp_w3 = (const float*)d_in[24];
    const float* mlp_b3 = (const float*)d_in[25];
    const float* mlp_w4 = (const float*)d_in[26];
    const float* mlp_b4 = (const float*)d_in[27];

    int B = in_sizes[0];
    int nb = (B + 127) / 128;
    int nb1 = (5 * B + 127) / 128;

    cudaFuncSetAttribute((const void*)t1_score,
                         cudaFuncAttributeMaxDynamicSharedMemorySize, T1_SMEM);
    cudaFuncSetAttribute((const void*)t2_mlp,
                         cudaFuncAttributeMaxDynamicSharedMemorySize, T2_SMEM);

    prep_tables<<<228, 256>>>(act_w1, act_w2, mlp_w1, mlp_w2, mlp_w3, kind_emb);

    k0_feat<<<nb, 128>>>(userid, itemid, user_age, gender, user_occ, item_kind,
                         user_emb, item_emb, age_emb, gen_emb, occ_emb, kind_emb,
                         act_b1, B);

    t1_score<<<nb1, 512, T1_SMEM>>>(his_id, his_kind, item_emb, kind_emb,
                                    act_b2, act_w3, act_b3, B);

    k2_pool<<<nb, 128>>>(his_id, his_kind, item_emb, kind_emb, B);

    t2_mlp<<<nb, 512, T2_SMEM>>>(mlp_b1, mlp_b2, mlp_b3, mlp_w4, mlp_b4,
                                 (float*)d_out, B);
}

// round 13
// speedup vs baseline: 1.0790x; 1.0790x over previous
#include <cuda_runtime.h>
#include <cuda_fp16.h>
#include <mma.h>
#include <math.h>

using namespace nvcuda;

#define BMAX 65536
#define HIS 5
#define KINDS 10

// ---------------------------------------------------------------------------
// Device scratch
// ---------------------------------------------------------------------------
static __device__ __half2 g_af2h[104u * BMAX];
static __device__ __half2 g_af2l[104u * BMAX];
static __device__ float   g_baseS[64u * BMAX];     // sample-major base [b][64]
static __device__ float   g_score[HIS * BMAX];

// Tables / prepped weights
static __device__ float  g_Wc0[64 * 8];            // (W1c-W1b)[:,0:8]
static __device__ float  g_Tc[10 * 16 * 20 * 4];   // [j][o4][kk] float4
// Transposed split fp16 weights, [k][n] row-major:
static __device__ __half g_w1th[208 * 128];
static __device__ __half g_w1tl[208 * 128];
static __device__ __half g_w2th[128 * 64];
static __device__ __half g_w2tl[128 * 64];
static __device__ __half g_w3th[64 * 32];
static __device__ __half g_w3tl[64 * 32];
// ActUnit: Wa = W1a+W1b transposed [k=96(pad)][n=64]; act_w2 transposed [64][32]
static __device__ __half g_wa1th[96 * 64];
static __device__ __half g_wa1tl[96 * 64];
static __device__ __half g_aw2th[64 * 32];
static __device__ __half g_aw2tl[64 * 32];

__device__ __forceinline__ float4 ldg4(const float* p) {
    return __ldg((const float4*)p);
}

__device__ __forceinline__ void st_feat(int B, int b, int rp, float x, float y) {
    __half hx = __float2half_rn(x), hy = __float2half_rn(y);
    float lx = x - __half2float(hx), ly = y - __half2float(hy);
    g_af2h[(size_t)rp * (size_t)B + (size_t)b] = __halves2half2(hx, hy);
    g_af2l[(size_t)rp * (size_t)B + (size_t)b] =
        __halves2half2(__float2half_rn(lx), __float2half_rn(ly));
}

__device__ __forceinline__ void st8(int B, int b, int rp, float4 v0, float4 v1) {
    st_feat(B, b, rp + 0, v0.x, v0.y);
    st_feat(B, b, rp + 1, v0.z, v0.w);
    st_feat(B, b, rp + 2, v1.x, v1.y);
    st_feat(B, b, rp + 3, v1.z, v1.w);
}

// ---------------------------------------------------------------------------
// prep
// ---------------------------------------------------------------------------
extern "C" __global__ void prep_tables(const float* __restrict__ act_w1,
                                       const float* __restrict__ act_w2,
                                       const float* __restrict__ mlp_w1,
                                       const float* __restrict__ mlp_w2,
                                       const float* __restrict__ mlp_w3,
                                       const float* __restrict__ kind_emb)
{
    int i = blockIdx.x * blockDim.x + threadIdx.x;
    if (i < 512) {
        int o = i >> 3, d = i & 7;
        const float* r = act_w1 + o * 264;
        g_Wc0[o * 8 + d] = r[176 + d] - r[88 + d];
        return;
    }
    i -= 512;
    if (i < 12800) {
        int f = i & 3; int r1 = i >> 2;
        int kk = r1 % 20; r1 /= 20;
        int o4 = r1 % 16; int j = r1 / 16;
        int o = 4 * o4 + f;
        float v = 0.f;
        if (kk != 0) {
            const float* r = act_w1 + o * 264 + 8 * (j + 1);
            const float* e = kind_emb + kk * 8;
            #pragma unroll
            for (int d = 0; d < 8; d++)
                v += (r[176 + d] - r[88 + d]) * e[d];
        }
        g_Tc[i] = v;
        return;
    }
    i -= 12800;
    if (i < 26624) {                    // w1t: [k=208][n=128]
        int k = i >> 7, n = i & 127;
        float w = mlp_w1[n * 208 + k];
        __half h = __float2half_rn(w);
        g_w1th[i] = h;
        g_w1tl[i] = __float2half_rn(w - __half2float(h));
        return;
    }
    i -= 26624;
    if (i < 8192) {                     // w2t: [k=128][n=64]
        int k = i >> 6, n = i & 63;
        float w = mlp_w2[n * 128 + k];
        __half h = __float2half_rn(w);
        g_w2th[i] = h;
        g_w2tl[i] = __float2half_rn(w - __half2float(h));
        return;
    }
    i -= 8192;
    if (i < 2048) {                     // w3t: [k=64][n=32]
        int k = i >> 5, n = i & 31;
        float w = mlp_w3[n * 64 + k];
        __half h = __float2half_rn(w);
        g_w3th[i] = h;
        g_w3tl[i] = __float2half_rn(w - __half2float(h));
        return;
    }
    i -= 2048;
    if (i < 6144) {                     // wa1t: [k=96][n=64], k>=88 zero
        int k = i >> 6, n = i & 63;
        float w = 0.f;
        if (k < 88) {
            const float* r = act_w1 + n * 264;
            w = r[k] + r[88 + k];
        }
        __half h = __float2half_rn(w);
        g_wa1th[i] = h;
        g_wa1tl[i] = __float2half_rn(w - __half2float(h));
        return;
    }
    i -= 6144;
    if (i < 2048) {                     // aw2t: [k=64][n=32]
        int k = i >> 5, n = i & 31;
        float w = act_w2[n * 64 + k];
        __half h = __float2half_rn(w);
        g_aw2th[i] = h;
        g_aw2tl[i] = __float2half_rn(w - __half2float(h));
    }
}

// ---------------------------------------------------------------------------
// k0: gathers -> split fp16 all_feat rows 0..119, base -> g_baseS (sample-major).
// ---------------------------------------------------------------------------
extern "C" __global__ void __launch_bounds__(128, 4)
k0_feat(const int* __restrict__ userid, const int* __restrict__ itemid,
        const int* __restrict__ user_age, const int* __restrict__ gender,
        const int* __restrict__ user_occ, const int* __restrict__ item_kind,
        const float* __restrict__ user_emb, const float* __restrict__ item_emb,
        const float* __restrict__ age_emb, const float* __restrict__ gender_emb,
        const float* __restrict__ occ_emb, const float* __restrict__ kind_emb,
        const float* __restrict__ act_b1, int B)
{
    __shared__ float sWc0[64 * 8];
    for (int idx = threadIdx.x; idx < 512; idx += blockDim.x) sWc0[idx] = g_Wc0[idx];
    __syncthreads();

    int b = blockIdx.x * blockDim.x + threadIdx.x;
    if (b >= B) return;

    float4 iv0, iv1;
    {
        const float* p = user_emb + (size_t)userid[b] * 8;
        st8(B, b, 0, ldg4(p), ldg4(p + 4));
        p = item_emb + (size_t)itemid[b] * 8;
        iv0 = ldg4(p); iv1 = ldg4(p + 4);
        st8(B, b, 4, iv0, iv1);
        p = age_emb + (size_t)user_age[b] * 8;
        st8(B, b, 8, ldg4(p), ldg4(p + 4));
        p = gender_emb + (size_t)gender[b] * 8;
        st8(B, b, 12, ldg4(p), ldg4(p + 4));
        p = occ_emb + (size_t)user_occ[b] * 8;
        st8(B, b, 16, ldg4(p), ldg4(p + 4));
    }

    float acc[64];
    #pragma unroll
    for (int o = 0; o < 64; o++) acc[o] = __ldg(act_b1 + o);

    #pragma unroll
    for (int o = 0; o < 64; o++) {
        float4 w0 = *(const float4*)(sWc0 + o * 8);
        float4 w1 = *(const float4*)(sWc0 + o * 8 + 4);
        acc[o] += w0.x*iv0.x + w0.y*iv0.y + w0.z*iv0.z + w0.w*iv0.w
                + w1.x*iv1.x + w1.y*iv1.y + w1.z*iv1.z + w1.w*iv1.w;
    }

    #pragma unroll 1
    for (int j = 0; j < 10; j++) {
        int kk = item_kind[b * KINDS + j];
        const float* p = kind_emb + (size_t)kk * 8;
        float4 v0 = ldg4(p), v1 = ldg4(p + 4);
        if (kk == 0) { v0 = make_float4(0.f,0.f,0.f,0.f); v1 = v0; }
        st8(B, b, 20 + 4 * j, v0, v1);
        const float4* t = (const float4*)g_Tc + (size_t)(j * 16) * 20 + kk;
        #pragma unroll
        for (int o4 = 0; o4 < 16; o4++) {
            float4 v = __ldg(t + o4 * 20);
            acc[4*o4+0] += v.x; acc[4*o4+1] += v.y;
            acc[4*o4+2] += v.z; acc[4*o4+3] += v.w;
        }
    }

    float* bp = g_baseS + (size_t)b * 64;
    #pragma unroll
    for (int o4 = 0; o4 < 16; o4++)
        *(float4*)(bp + 4*o4) = make_float4(acc[4*o4], acc[4*o4+1],
                                            acc[4*o4+2], acc[4*o4+3]);
}

// ---------------------------------------------------------------------------
// t1_score v2: ActUnit via split-fp16 wmma. 128 (b,s) rows / block, 512 threads,
// weights smem-resident, aliased buffers, 2 blocks/SM.
// ---------------------------------------------------------------------------
#define T1_SMEM 102400

extern "C" __global__ void __launch_bounds__(512, 2)
t1_score(const int* __restrict__ his_id, const int* __restrict__ his_kind,
         const float* __restrict__ item_emb, const float* __restrict__ kind_emb,
         const float* __restrict__ act_b2, const float* __restrict__ act_w3,
         const float* __restrict__ act_b3, int B)
{
    extern __shared__ char smem[];
    __half* sAH   = (__half*)(smem);            // [96][136]  (phase 1-2)
    __half* sAL   = (__half*)(smem + 26112);
    __half* sA2H  = (__half*)(smem);            // [128][72]  (alias, phase 3+)
    __half* sA2L  = (__half*)(smem + 18432);
    __half* sWa1H = (__half*)(smem + 52224);    // [96][64]
    __half* sWa1L = (__half*)(smem + 64512);
    __half* sW2H  = (__half*)(smem + 76800);    // [64][32]
    __half* sW2L  = (__half*)(smem + 80896);
    float*  sScr  = (float*)(smem + 84992);     // [16][256]
    float*  sPart = (float*)(smem + 101376);    // [128][2]

    int tid = threadIdx.x;
    int w = tid >> 5, lane = tid & 31;
    int mr = w >> 1, nh = w & 1;
    int m0w = mr * 16;
    int m0g = blockIdx.x * 128;
    int NG = 5 * B;
    float* scr = sScr + w * 256;

    typedef wmma::fragment<wmma::matrix_a, 16,16,16, __half, wmma::col_major> FragAc;
    typedef wmma::fragment<wmma::matrix_a, 16,16,16, __half, wmma::row_major> FragAr;
    typedef wmma::fragment<wmma::matrix_b, 16,16,16, __half, wmma::row_major> FragB;
    typedef wmma::fragment<wmma::accumulator, 16,16,16, float> FragC;

    // stage weights (coalesced as half2)
    for (int i = tid; i < 3072; i += 512) {
        ((__half2*)sWa1H)[i] = ((const __half2*)g_wa1th)[i];
        ((__half2*)sWa1L)[i] = ((const __half2*)g_wa1tl)[i];
    }
    for (int i = tid; i < 1024; i += 512) {
        ((__half2*)sW2H)[i] = ((const __half2*)g_aw2th)[i];
        ((__half2*)sW2L)[i] = ((const __half2*)g_aw2tl)[i];
    }
    // zero pad rows k=88..95
    for (int i = tid; i < 1088; i += 512) {
        sAH[11968 + i] = __float2half_rn(0.f);
        sAL[11968 + i] = __float2half_rn(0.f);
    }

    // gather features: 4 threads per row, chunks j = q, q+4, q+8
    {
        int r = tid >> 2, q = tid & 3;
        int g = m0g + r;
        if (g >= NG) g = NG - 1;
        int hid = __ldg(his_id + g);
        #pragma unroll
        for (int jj = 0; jj < 3; jj++) {
            int j = q + jj * 4;
            if (j >= 11) break;
            const float* p;
            float mk = 1.f;
            if (j == 0) {
                p = item_emb + (size_t)hid * 8;
            } else {
                int kk = __ldg(his_kind + (size_t)g * KINDS + (j - 1));
                p = kind_emb + (size_t)kk * 8;
                mk = (kk != 0) ? 1.f : 0.f;
            }
            float4 v0 = ldg4(p), v1 = ldg4(p + 4);
            float vv[8] = {v0.x*mk, v0.y*mk, v0.z*mk, v0.w*mk,
                           v1.x*mk, v1.y*mk, v1.z*mk, v1.w*mk};
            #pragma unroll
            for (int d = 0; d < 8; d++) {
                float x = vv[d];
                __half h = __float2half_rn(x);
                sAH[(8*j + d) * 136 + r] = h;
                sAL[(8*j + d) * 136 + r] = __float2half_rn(x - __half2float(h));
            }
        }
    }
    __syncthreads();

    // ===== Layer 1: [128x96] @ [96x64] =====
    FragC acc[2];
    #pragma unroll
    for (int c = 0; c < 2; c++) wmma::fill_fragment(acc[c], 0.0f);
    int n0base = nh * 32;

    #pragma unroll 1
    for (int t = 0; t < 6; t++) {
        FragAc ah, al;
        wmma::load_matrix_sync(ah, sAH + (16*t)*136 + m0w, 136);
        wmma::load_matrix_sync(al, sAL + (16*t)*136 + m0w, 136);
        #pragma unroll
        for (int c = 0; c < 2; c++) {
            FragB bh, bl;
            wmma::load_matrix_sync(bh, sWa1H + (16*t)*64 + n0base + 16*c, 64);
            wmma::load_matrix_sync(bl, sWa1L + (16*t)*64 + n0base + 16*c, 64);
            wmma::mma_sync(acc[c], ah, bh, acc[c]);
            wmma::mma_sync(acc[c], ah, bl, acc[c]);
            wmma::mma_sync(acc[c], al, bh, acc[c]);
        }
    }
    __syncthreads();   // before aliased sA2 writes over sAH/sAL

    // epilogue L1: + base (sample-major, coalesced) + relu + split -> sA2
    #pragma unroll 1
    for (int c = 0; c < 2; c++) {
        __syncwarp();
        wmma::store_matrix_sync(scr, acc[c], 16, wmma::mem_row_major);
        __syncwarp();
        int n0 = n0base + 16 * c;
        #pragma unroll
        for (int i = 0; i < 8; i++) {
            int idx = i * 32 + lane;
            int r = idx >> 4, cc = idx & 15;
            int m = m0w + r, n = n0 + cc;
            int g2 = m0g + m;
            if (g2 >= NG) g2 = NG - 1;
            int b = g2 / 5;
            float v = scr[idx] + __ldg(g_baseS + (size_t)b * 64 + n);
            v = fmaxf(v, 0.f);
            __half h = __float2half_rn(v);
            sA2H[m * 72 + n] = h;
            sA2L[m * 72 + n] = __float2half_rn(v - __half2float(h));
        }
    }
    __syncthreads();

    // ===== Layer 2: [128x64] @ [64x32] =====
    FragC acc2;
    wmma::fill_fragment(acc2, 0.0f);
    int n03 = nh * 16;

    #pragma unroll 1
    for (int t = 0; t < 4; t++) {
        FragAr ah, al;
        wmma::load_matrix_sync(ah, sA2H + m0w * 72 + 16 * t, 72);
        wmma::load_matrix_sync(al, sA2L + m0w * 72 + 16 * t, 72);
        FragB bh, bl;
        wmma::load_matrix_sync(bh, sW2H + (16*t)*32 + n03, 32);
        wmma::load_matrix_sync(bl, sW2L + (16*t)*32 + n03, 32);
        wmma::mma_sync(acc2, ah, bh, acc2);
        wmma::mma_sync(acc2, ah, bl, acc2);
        wmma::mma_sync(acc2, al, bh, acc2);
    }
    __syncwarp();
    wmma::store_matrix_sync(scr, acc2, 16, wmma::mem_row_major);
    __syncwarp();

    // partial dot over this warp's 16 output cols (bias+relu+w3 inline)
    if (lane < 16) {
        int r = lane;
        float p = 0.f;
        #pragma unroll
        for (int cc = 0; cc < 16; cc++) {
            int n = n03 + cc;
            float v = scr[r * 16 + cc] + __ldg(act_b2 + n);
            p += __ldg(act_w3 + n) * fmaxf(v, 0.f);
        }
        sPart[(m0w + r) * 2 + nh] = p;
    }
    __syncthreads();

    // ===== finalize scores =====
    if (tid < 128) {
        int g2 = m0g + tid;
        if (g2 < NG) {
            float sc = __ldg(act_b3) + sPart[tid * 2] + sPart[tid * 2 + 1];
            int b = g2 / 5, s = g2 - 5 * b;
            g_score[(size_t)s * (size_t)B + (size_t)b] = sc;
        }
    }
}

// ---------------------------------------------------------------------------
// k2: his_pool -> split fp16 rows 120..207 (rowpairs 60..103).
// ---------------------------------------------------------------------------
extern "C" __global__ void __launch_bounds__(128, 4)
k2_pool(const int* __restrict__ his_id, const int* __restrict__ his_kind,
        const float* __restrict__ item_emb, const float* __restrict__ kind_emb,
        int B)
{
    int b = blockIdx.x * blockDim.x + threadIdx.x;
    if (b >= B) return;
    size_t sB = (size_t)B;

    float poolL[88];
    #pragma unroll
    for (int d = 0; d < 88; d++) poolL[d] = 0.f;

    #pragma unroll 1
    for (int s = 0; s < HIS; s++) {
        float sc = g_score[(size_t)s * sB + (size_t)b];
        int hid = his_id[b * HIS + s];
        {
            const float* p = item_emb + (size_t)hid * 8;
            float4 v0 = ldg4(p), v1 = ldg4(p + 4);
            poolL[0] += v0.x*v0.x*sc; poolL[1] += v0.y*v0.y*sc;
            poolL[2] += v0.z*v0.z*sc; poolL[3] += v0.w*v0.w*sc;
            poolL[4] += v1.x*v1.x*sc; poolL[5] += v1.y*v1.y*sc;
            poolL[6] += v1.z*v1.z*sc; poolL[7] += v1.w*v1.w*sc;
        }
        #pragma unroll
        for (int j = 0; j < 10; j++) {
            int kk = his_kind[(b * HIS + s) * KINDS + j];
            const float* p = kind_emb + (size_t)kk * 8;
            float4 v0 = ldg4(p), v1 = ldg4(p + 4);
            float fm = (kk != 0) ? sc : 0.f;
            int pp = 8 + j * 8;
            poolL[pp+0] += v0.x*v0.x*fm; poolL[pp+1] += v0.y*v0.y*fm;
            poolL[pp+2] += v0.z*v0.z*fm; poolL[pp+3] += v0.w*v0.w*fm;
            poolL[pp+4] += v1.x*v1.x*fm; poolL[pp+5] += v1.y*v1.y*fm;
            poolL[pp+6] += v1.z*v1.z*fm; poolL[pp+7] += v1.w*v1.w*fm;
        }
    }
    #pragma unroll 1
    for (int d = 0; d < 44; d++)
        st_feat(B, b, 60 + d, poolL[2*d], poolL[2*d + 1]);
}

// ---------------------------------------------------------------------------
// t2_mlp: fused 208->128->64->32->1 + sigmoid via split-fp16 wmma. (R11 proven)
// ---------------------------------------------------------------------------
#define T2_SMEM 157184

extern "C" __global__ void __launch_bounds__(512, 1)
t2_mlp(const float* __restrict__ mlp_b1, const float* __restrict__ mlp_b2,
       const float* __restrict__ mlp_b3, const float* __restrict__ mlp_w4,
       const float* __restrict__ mlp_b4, float* __restrict__ out, int B)
{
    extern __shared__ char smem[];
    __half* sAkH = (__half*)(smem + 0);        // [16][136]
    __half* sAkL = (__half*)(smem + 4352);
    __half* sBkH = (__half*)(smem + 8704);     // [16][136]
    __half* sBkL = (__half*)(smem + 13056);
    __half* sA2H = (__half*)(smem + 17408);    // [128][136]
    __half* sA2L = (__half*)(smem + 52224);
    __half* sA3H = (__half*)(smem + 87040);    // [128][72]
    __half* sA3L = (__half*)(smem + 105472);
    float*  sScr = (float*)(smem + 123904);    // [16][256]
    float*  sH3  = (float*)(smem + 140288);    // [128][33]

    int tid = threadIdx.x;
    int w = tid >> 5, lane = tid & 31;
    int m0 = blockIdx.x * 128;
    int mr = w >> 1;
    int m0w = mr * 16;
    float* scr = sScr + w * 256;

    typedef wmma::fragment<wmma::matrix_a, 16,16,16, __half, wmma::col_major> FragAc;
    typedef wmma::fragment<wmma::matrix_a, 16,16,16, __half, wmma::row_major> FragAr;
    typedef wmma::fragment<wmma::matrix_b, 16,16,16, __half, wmma::row_major> FragB;
    typedef wmma::fragment<wmma::accumulator, 16,16,16, float> FragC;

    FragC acc[4];
    #pragma unroll
    for (int c = 0; c < 4; c++) wmma::fill_fragment(acc[c], 0.0f);
    int nb1 = (w & 1) * 4;

    #pragma unroll 1
    for (int t = 0; t < 13; t++) {
        __syncthreads();
        #pragma unroll
        for (int i = tid; i < 1024; i += 512) {
            int j = i >> 7, m = i & 127;
            size_t src = (size_t)(8 * t + j) * (size_t)B + (size_t)(m0 + m);
            __half2 vh = g_af2h[src];
            __half2 vl = g_af2l[src];
            sAkH[(2*j) * 136 + m]     = __low2half(vh);
            sAkH[(2*j + 1) * 136 + m] = __high2half(vh);
            sAkL[(2*j) * 136 + m]     = __low2half(vl);
            sAkL[(2*j + 1) * 136 + m] = __high2half(vl);
        }
        #pragma unroll
        for (int i = tid; i < 1024; i += 512) {
            int kk = i >> 6, c2 = i & 63;
            *(__half2*)&sBkH[kk * 136 + 2 * c2] =
                ((const __half2*)g_w1th)[(16 * t + kk) * 64 + c2];
            *(__half2*)&sBkL[kk * 136 + 2 * c2] =
                ((const __half2*)g_w1tl)[(16 * t + kk) * 64 + c2];
        }
        __syncthreads();

        FragAc ah, al;
        wmma::load_matrix_sync(ah, sAkH + m0w, 136);
        wmma::load_matrix_sync(al, sAkL + m0w, 136);
        #pragma unroll
        for (int c = 0; c < 4; c++) {
            int n0 = (nb1 + c) * 16;
            FragB bh, bl;
            wmma::load_matrix_sync(bh, sBkH + n0, 136);
            wmma::load_matrix_sync(bl, sBkL + n0, 136);
            wmma::mma_sync(acc[c], ah, bh, acc[c]);
            wmma::mma_sync(acc[c], ah, bl, acc[c]);
            wmma::mma_sync(acc[c], al, bh, acc[c]);
        }
    }
    #pragma unroll 1
    for (int c = 0; c < 4; c++) {
        __syncwarp();
        wmma::store_matrix_sync(scr, acc[c], 16, wmma::mem_row_major);
        __syncwarp();
        int n0 = (nb1 + c) * 16;
        #pragma unroll
        for (int i = 0; i < 8; i++) {
            int idx = i * 32 + lane;
            int r = idx >> 4, cc = idx & 15;
            int n = n0 + cc, m = m0w + r;
            float v = scr[idx] + __ldg(mlp_b1 + n);
            v = fmaxf(v, 0.f);
            __half hv = __float2half_rn(v);
            sA2H[m * 136 + n] = hv;
            sA2L[m * 136 + n] = __float2half_rn(v - __half2float(hv));
        }
    }
    __syncthreads();

    FragC acc2[2];
    #pragma unroll
    for (int c = 0; c < 2; c++) wmma::fill_fragment(acc2[c], 0.0f);
    int nb2 = (w & 1) * 2;

    #pragma unroll 1
    for (int t = 0; t < 8; t++) {
        __syncthreads();
        if (tid < 512) {
            int kk = tid >> 5, c2 = tid & 31;
            *(__half2*)&sBkH[kk * 136 + 2 * c2] =
                ((const __half2*)g_w2th)[(16 * t + kk) * 32 + c2];
            *(__half2*)&sBkL[kk * 136 + 2 * c2] =
                ((const __half2*)g_w2tl)[(16 * t + kk) * 32 + c2];
        }
        __syncthreads();

        FragAr ah, al;
        wmma::load_matrix_sync(ah, sA2H + m0w * 136 + 16 * t, 136);
        wmma::load_matrix_sync(al, sA2L + m0w * 136 + 16 * t, 136);
        #pragma unroll
        for (int c = 0; c < 2; c++) {
            int n0 = (nb2 + c) * 16;
            FragB bh, bl;
            wmma::load_matrix_sync(bh, sBkH + n0, 136);
            wmma::load_matrix_sync(bl, sBkL + n0, 136);
            wmma::mma_sync(acc2[c], ah, bh, acc2[c]);
            wmma::mma_sync(acc2[c], ah, bl, acc2[c]);
            wmma::mma_sync(acc2[c], al, bh, acc2[c]);
        }
    }
    #pragma unroll 1
    for (int c = 0; c < 2; c++) {
        __syncwarp();
        wmma::store_matrix_sync(scr, acc2[c], 16, wmma::mem_row_major);
        __syncwarp();
        int n0 = (nb2 + c) * 16;
        #pragma unroll
        for (int i = 0; i < 8; i++) {
            int idx = i * 32 + lane;
            int r = idx >> 4, cc = idx & 15;
            int n = n0 + cc, m = m0w + r;
            float v = scr[idx] + __ldg(mlp_b2 + n);
            v = fmaxf(v, 0.f);
            __half hv = __float2half_rn(v);
            sA3H[m * 72 + n] = hv;
            sA3L[m * 72 + n] = __float2half_rn(v - __half2float(hv));
        }
    }
    __syncthreads();

    FragC acc3;
    wmma::fill_fragment(acc3, 0.0f);
    int n03 = (w & 1) * 16;

    #pragma unroll 1
    for (int t = 0; t < 4; t++) {
        __syncthreads();
        if (tid < 256) {
            int kk = tid >> 4, c2 = tid & 15;
            *(__half2*)&sBkH[kk * 136 + 2 * c2] =
                ((const __half2*)g_w3th)[(16 * t + kk) * 16 + c2];
            *(__half2*)&sBkL[kk * 136 + 2 * c2] =
                ((const __half2*)g_w3tl)[(16 * t + kk) * 16 + c2];
        }
        __syncthreads();

        FragAr ah, al;
        wmma::load_matrix_sync(ah, sA3H + m0w * 72 + 16 * t, 72);
        wmma::load_matrix_sync(al, sA3L + m0w * 72 + 16 * t, 72);
        FragB bh, bl;
        wmma::load_matrix_sync(bh, sBkH + n03, 136);
        wmma::load_matrix_sync(bl, sBkL + n03, 136);
        wmma::mma_sync(acc3, ah, bh, acc3);
        wmma::mma_sync(acc3, ah, bl, acc3);
        wmma::mma_sync(acc3, al, bh, acc3);
    }
    __syncwarp();
    wmma::store_matrix_sync(scr, acc3, 16, wmma::mem_row_major);
    __syncwarp();
    #pragma unroll
    for (int i = 0; i < 8; i++) {
        int idx = i * 32 + lane;
        int r = idx >> 4, cc = idx & 15;
        int n = n03 + cc, m = m0w + r;
        float v = scr[idx] + __ldg(mlp_b3 + n);
        sH3[m * 33 + n] = fmaxf(v, 0.f);
    }
    __syncthreads();

    if (tid < 128) {
        int m = tid;
        float logit = __ldg(mlp_b4);
        #pragma unroll
        for (int o = 0; o < 32; o++)
            logit += __ldg(mlp_w4 + o) * sH3[m * 33 + o];
        out[m0 + m] = 1.f / (1.f + expf(-logit));
    }
}

// ---------------------------------------------------------------------------
extern "C" void kernel_launch(void* const* d_in, const int* in_sizes, int n_in,
                              void* d_out, int out_size)
{
    const int*   userid   = (const int*)d_in[0];
    const int*   itemid   = (const int*)d_in[1];
    const int*   user_age = (const int*)d_in[2];
    const int*   gender   = (const int*)d_in[3];
    const int*   user_occ = (const int*)d_in[4];
    const int*   item_kind= (const int*)d_in[5];
    const int*   his_id   = (const int*)d_in[6];
    const int*   his_kind = (const int*)d_in[7];
    const float* user_emb = (const float*)d_in[8];
    const float* item_emb = (const float*)d_in[9];
    const float* age_emb  = (const float*)d_in[10];
    const float* gen_emb  = (const float*)d_in[11];
    const float* occ_emb  = (const float*)d_in[12];
    const float* kind_emb = (const float*)d_in[13];
    const float* act_w1 = (const float*)d_in[14];
    const float* act_b1 = (const float*)d_in[15];
    const float* act_w2 = (const float*)d_in[16];
    const float* act_b2 = (const float*)d_in[17];
    const float* act_w3 = (const float*)d_in[18];
    const float* act_b3 = (const float*)d_in[19];
    const float* mlp_w1 = (const float*)d_in[20];
    const float* mlp_b1 = (const float*)d_in[21];
    const float* mlp_w2 = (const float*)d_in[22];
    const float* mlp_b2 = (const float*)d_in[23];
    const float* mlp_w3 = (const float*)d_in[24];
    const float* mlp_b3 = (const float*)d_in[25];
    const float* mlp_w4 = (const float*)d_in[26];
    const float* mlp_b4 = (const float*)d_in[27];

    int B = in_sizes[0];
    int nb = (B + 127) / 128;
    int nb1 = (5 * B + 127) / 128;

    cudaFuncSetAttribute((const void*)t1_score,
                         cudaFuncAttributeMaxDynamicSharedMemorySize, T1_SMEM);
    cudaFuncSetAttribute((const void*)t2_mlp,
                         cudaFuncAttributeMaxDynamicSharedMemorySize, T2_SMEM);

    prep_tables<<<228, 256>>>(act_w1, act_w2, mlp_w1, mlp_w2, mlp_w3, kind_emb);

    k0_feat<<<nb, 128>>>(userid, itemid, user_age, gender, user_occ, item_kind,
                         user_emb, item_emb, age_emb, gen_emb, occ_emb, kind_emb,
                         act_b1, B);

    t1_score<<<nb1, 512, T1_SMEM>>>(his_id, his_kind, item_emb, kind_emb,
                                    act_b2, act_w3, act_b3, B);

    k2_pool<<<nb, 128>>>(his_id, his_kind, item_emb, kind_emb, B);

    t2_mlp<<<nb, 512, T2_SMEM>>>(mlp_b1, mlp_b2, mlp_b3, mlp_w4, mlp_b4,
                                 (float*)d_out, B);
}

// round 14
// speedup vs baseline: 1.1200x; 1.0380x over previous
#include <cuda_runtime.h>
#include <cuda_fp16.h>
#include <mma.h>
#include <math.h>

using namespace nvcuda;

#define BMAX 65536
#define HIS 5
#define KINDS 10

// ---------------------------------------------------------------------------
// Device scratch
// ---------------------------------------------------------------------------
static __device__ __half2 g_af2h[104u * BMAX];
static __device__ __half2 g_af2l[104u * BMAX];
static __device__ float2  g_base2[32u * BMAX];     // 64 scalar rows fp32

// Tables / prepped weights
static __device__ float  g_Wc0[64 * 8];            // (W1c-W1b)[:,0:8]
static __device__ float  g_Tc[10 * 16 * 20 * 4];   // [j][o4][kk] float4
// Transposed split fp16 weights, [k][n] row-major:
static __device__ __half g_w1th[208 * 128];
static __device__ __half g_w1tl[208 * 128];
static __device__ __half g_w2th[128 * 64];
static __device__ __half g_w2tl[128 * 64];
static __device__ __half g_w3th[64 * 32];
static __device__ __half g_w3tl[64 * 32];

__device__ __forceinline__ float4 ldg4(const float* p) {
    return __ldg((const float4*)p);
}

__device__ __forceinline__ void st_feat(int B, int b, int rp, float x, float y) {
    __half hx = __float2half_rn(x), hy = __float2half_rn(y);
    float lx = x - __half2float(hx), ly = y - __half2float(hy);
    g_af2h[(size_t)rp * (size_t)B + (size_t)b] = __halves2half2(hx, hy);
    g_af2l[(size_t)rp * (size_t)B + (size_t)b] =
        __halves2half2(__float2half_rn(lx), __float2half_rn(ly));
}

__device__ __forceinline__ void st8(int B, int b, int rp, float4 v0, float4 v1) {
    st_feat(B, b, rp + 0, v0.x, v0.y);
    st_feat(B, b, rp + 1, v0.z, v0.w);
    st_feat(B, b, rp + 2, v1.x, v1.y);
    st_feat(B, b, rp + 3, v1.z, v1.w);
}

// ---------------------------------------------------------------------------
// prep: 512 + 12800 + 26624 + 8192 + 2048 = 50176 outputs.
// ---------------------------------------------------------------------------
extern "C" __global__ void prep_tables(const float* __restrict__ act_w1,
                                       const float* __restrict__ mlp_w1,
                                       const float* __restrict__ mlp_w2,
                                       const float* __restrict__ mlp_w3,
                                       const float* __restrict__ kind_emb)
{
    int i = blockIdx.x * blockDim.x + threadIdx.x;
    if (i < 512) {
        int o = i >> 3, d = i & 7;
        const float* r = act_w1 + o * 264;
        g_Wc0[o * 8 + d] = r[176 + d] - r[88 + d];
        return;
    }
    i -= 512;
    if (i < 12800) {
        int f = i & 3; int r1 = i >> 2;
        int kk = r1 % 20; r1 /= 20;
        int o4 = r1 % 16; int j = r1 / 16;
        int o = 4 * o4 + f;
        float v = 0.f;
        if (kk != 0) {
            const float* r = act_w1 + o * 264 + 8 * (j + 1);
            const float* e = kind_emb + kk * 8;
            #pragma unroll
            for (int d = 0; d < 8; d++)
                v += (r[176 + d] - r[88 + d]) * e[d];
        }
        g_Tc[i] = v;
        return;
    }
    i -= 12800;
    if (i < 26624) {                    // w1t: [k=208][n=128]
        int k = i >> 7, n = i & 127;
        float w = mlp_w1[n * 208 + k];
        __half h = __float2half_rn(w);
        g_w1th[i] = h;
        g_w1tl[i] = __float2half_rn(w - __half2float(h));
        return;
    }
    i -= 26624;
    if (i < 8192) {                     // w2t: [k=128][n=64]
        int k = i >> 6, n = i & 63;
        float w = mlp_w2[n * 128 + k];
        __half h = __float2half_rn(w);
        g_w2th[i] = h;
        g_w2tl[i] = __float2half_rn(w - __half2float(h));
        return;
    }
    i -= 8192;
    if (i < 2048) {                     // w3t: [k=64][n=32]
        int k = i >> 5, n = i & 31;
        float w = mlp_w3[n * 64 + k];
        __half h = __float2half_rn(w);
        g_w3th[i] = h;
        g_w3tl[i] = __float2half_rn(w - __half2float(h));
    }
}

// ---------------------------------------------------------------------------
// k0: gathers -> split fp16 all_feat rows 0..119, base -> g_base2 (fp32).
// ---------------------------------------------------------------------------
extern "C" __global__ void __launch_bounds__(128, 4)
k0_feat(const int* __restrict__ userid, const int* __restrict__ itemid,
        const int* __restrict__ user_age, const int* __restrict__ gender,
        const int* __restrict__ user_occ, const int* __restrict__ item_kind,
        const float* __restrict__ user_emb, const float* __restrict__ item_emb,
        const float* __restrict__ age_emb, const float* __restrict__ gender_emb,
        const float* __restrict__ occ_emb, const float* __restrict__ kind_emb,
        const float* __restrict__ act_b1, int B)
{
    __shared__ float sWc0[64 * 8];
    for (int idx = threadIdx.x; idx < 512; idx += blockDim.x) sWc0[idx] = g_Wc0[idx];
    __syncthreads();

    int b = blockIdx.x * blockDim.x + threadIdx.x;
    if (b >= B) return;
    size_t sB = (size_t)B;

    float4 iv0, iv1;
    {
        const float* p = user_emb + (size_t)userid[b] * 8;
        st8(B, b, 0, ldg4(p), ldg4(p + 4));
        p = item_emb + (size_t)itemid[b] * 8;
        iv0 = ldg4(p); iv1 = ldg4(p + 4);
        st8(B, b, 4, iv0, iv1);
        p = age_emb + (size_t)user_age[b] * 8;
        st8(B, b, 8, ldg4(p), ldg4(p + 4));
        p = gender_emb + (size_t)gender[b] * 8;
        st8(B, b, 12, ldg4(p), ldg4(p + 4));
        p = occ_emb + (size_t)user_occ[b] * 8;
        st8(B, b, 16, ldg4(p), ldg4(p + 4));
    }

    float acc[64];
    #pragma unroll
    for (int o = 0; o < 64; o++) acc[o] = __ldg(act_b1 + o);

    #pragma unroll
    for (int o = 0; o < 64; o++) {
        float4 w0 = *(const float4*)(sWc0 + o * 8);
        float4 w1 = *(const float4*)(sWc0 + o * 8 + 4);
        acc[o] += w0.x*iv0.x + w0.y*iv0.y + w0.z*iv0.z + w0.w*iv0.w
                + w1.x*iv1.x + w1.y*iv1.y + w1.z*iv1.z + w1.w*iv1.w;
    }

    #pragma unroll 1
    for (int j = 0; j < 10; j++) {
        int kk = item_kind[b * KINDS + j];
        const float* p = kind_emb + (size_t)kk * 8;
        float4 v0 = ldg4(p), v1 = ldg4(p + 4);
        if (kk == 0) { v0 = make_float4(0.f,0.f,0.f,0.f); v1 = v0; }
        st8(B, b, 20 + 4 * j, v0, v1);
        const float4* t = (const float4*)g_Tc + (size_t)(j * 16) * 20 + kk;
        #pragma unroll
        for (int o4 = 0; o4 < 16; o4++) {
            float4 v = __ldg(t + o4 * 20);
            acc[4*o4+0] += v.x; acc[4*o4+1] += v.y;
            acc[4*o4+2] += v.z; acc[4*o4+3] += v.w;
        }
    }

    float2* bp = g_base2 + (size_t)b;
    #pragma unroll
    for (int o = 0; o < 32; o++)
        bp[(size_t)o * sB] = make_float2(acc[2*o], acc[2*o + 1]);
}

// ---------------------------------------------------------------------------
// k1s_pool: all 5 attention scores (pass 1, R11-proven scalar FMA) + pooling
// (pass 2, L1-hot re-gather) in one kernel. Scores parked in smem.
// ---------------------------------------------------------------------------
extern "C" __global__ void __launch_bounds__(128, 4)
k1s_pool(const int* __restrict__ his_id, const int* __restrict__ his_kind,
         const float* __restrict__ item_emb, const float* __restrict__ kind_emb,
         const float* __restrict__ act_w1,
         const float* __restrict__ act_w2, const float* __restrict__ act_b2,
         const float* __restrict__ act_w3, const float* __restrict__ act_b3,
         int B)
{
    __shared__ float sWa[64 * 88];
    __shared__ float sW2[32 * 64];
    __shared__ float sB2[32];
    __shared__ float sW3[32];
    __shared__ float sB3s;
    __shared__ float sScore[HIS][128];

    for (int idx = threadIdx.x; idx < 64 * 88; idx += blockDim.x) {
        int o = idx / 88, k = idx - o * 88;
        const float* r = act_w1 + o * 264;
        sWa[idx] = r[k] + r[88 + k];
    }
    for (int idx = threadIdx.x; idx < 32 * 64; idx += blockDim.x) sW2[idx] = act_w2[idx];
    if (threadIdx.x < 32) { sB2[threadIdx.x] = act_b2[threadIdx.x];
                            sW3[threadIdx.x] = act_w3[threadIdx.x]; }
    if (threadIdx.x == 0) sB3s = act_b3[0];
    __syncthreads();

    int b = blockIdx.x * blockDim.x + threadIdx.x;
    if (b >= B) return;
    size_t sB = (size_t)B;

    // ===== pass 1: scores =====
    #pragma unroll 1
    for (int s = 0; s < HIS; s++) {
        float acc[64];
        {
            const float2* bp = g_base2 + (size_t)b;
            #pragma unroll
            for (int o = 0; o < 32; o++) {
                float2 v = bp[(size_t)o * sB];
                acc[2*o] = v.x; acc[2*o + 1] = v.y;
            }
        }

        int hid = his_id[b * HIS + s];
        #pragma unroll 1
        for (int j = 0; j < 11; j++) {
            float4 v0, v1;
            if (j == 0) {
                const float* p = item_emb + (size_t)hid * 8;
                v0 = ldg4(p); v1 = ldg4(p + 4);
            } else {
                int kk = his_kind[(b * HIS + s) * KINDS + (j - 1)];
                const float* p = kind_emb + (size_t)kk * 8;
                v0 = ldg4(p); v1 = ldg4(p + 4);
                float m = (kk != 0) ? 1.f : 0.f;
                v0.x*=m; v0.y*=m; v0.z*=m; v0.w*=m;
                v1.x*=m; v1.y*=m; v1.z*=m; v1.w*=m;
            }
            const float* wb = sWa + j * 8;
            #pragma unroll
            for (int o = 0; o < 64; o++) {
                float4 w0 = *(const float4*)(wb + o * 88);
                float4 w1 = *(const float4*)(wb + o * 88 + 4);
                acc[o] += w0.x*v0.x + w0.y*v0.y + w0.z*v0.z + w0.w*v0.w
                        + w1.x*v1.x + w1.y*v1.y + w1.z*v1.z + w1.w*v1.w;
            }
        }

        float acc2[32];
        #pragma unroll
        for (int o = 0; o < 32; o++) acc2[o] = sB2[o];
        #pragma unroll
        for (int kc = 0; kc < 16; kc++) {
            float a0 = fmaxf(acc[4*kc+0], 0.f);
            float a1 = fmaxf(acc[4*kc+1], 0.f);
            float a2 = fmaxf(acc[4*kc+2], 0.f);
            float a3 = fmaxf(acc[4*kc+3], 0.f);
            const float* wb = sW2 + 4 * kc;
            #pragma unroll
            for (int o = 0; o < 32; o++) {
                float4 w = *(const float4*)(wb + o * 64);
                acc2[o] += w.x*a0 + w.y*a1 + w.z*a2 + w.w*a3;
            }
        }
        float sc = sB3s;
        #pragma unroll
        for (int o = 0; o < 32; o++) sc += sW3[o] * fmaxf(acc2[o], 0.f);
        sScore[s][threadIdx.x] = sc;
    }

    // ===== pass 2: pooling (embeddings L1-hot from pass 1) =====
    float poolL[88];
    #pragma unroll
    for (int d = 0; d < 88; d++) poolL[d] = 0.f;

    #pragma unroll 1
    for (int s = 0; s < HIS; s++) {
        float sc = sScore[s][threadIdx.x];
        int hid = his_id[b * HIS + s];
        {
            const float* p = item_emb + (size_t)hid * 8;
            float4 v0 = ldg4(p), v1 = ldg4(p + 4);
            poolL[0] += v0.x*v0.x*sc; poolL[1] += v0.y*v0.y*sc;
            poolL[2] += v0.z*v0.z*sc; poolL[3] += v0.w*v0.w*sc;
            poolL[4] += v1.x*v1.x*sc; poolL[5] += v1.y*v1.y*sc;
            poolL[6] += v1.z*v1.z*sc; poolL[7] += v1.w*v1.w*sc;
        }
        #pragma unroll
        for (int j = 0; j < 10; j++) {
            int kk = his_kind[(b * HIS + s) * KINDS + j];
            const float* p = kind_emb + (size_t)kk * 8;
            float4 v0 = ldg4(p), v1 = ldg4(p + 4);
            float fm = (kk != 0) ? sc : 0.f;
            int pp = 8 + j * 8;
            poolL[pp+0] += v0.x*v0.x*fm; poolL[pp+1] += v0.y*v0.y*fm;
            poolL[pp+2] += v0.z*v0.z*fm; poolL[pp+3] += v0.w*v0.w*fm;
            poolL[pp+4] += v1.x*v1.x*fm; poolL[pp+5] += v1.y*v1.y*fm;
            poolL[pp+6] += v1.z*v1.z*fm; poolL[pp+7] += v1.w*v1.w*fm;
        }
    }
    #pragma unroll 1
    for (int d = 0; d < 44; d++)
        st_feat(B, b, 60 + d, poolL[2*d], poolL[2*d + 1]);
}

// ---------------------------------------------------------------------------
// t2_mlp: fused 208->128->64->32->1 + sigmoid via split-fp16 wmma. (R11 proven)
// ---------------------------------------------------------------------------
#define T2_SMEM 157184

extern "C" __global__ void __launch_bounds__(512, 1)
t2_mlp(const float* __restrict__ mlp_b1, const float* __restrict__ mlp_b2,
       const float* __restrict__ mlp_b3, const float* __restrict__ mlp_w4,
       const float* __restrict__ mlp_b4, float* __restrict__ out, int B)
{
    extern __shared__ char smem[];
    __half* sAkH = (__half*)(smem + 0);        // [16][136]
    __half* sAkL = (__half*)(smem + 4352);
    __half* sBkH = (__half*)(smem + 8704);     // [16][136]
    __half* sBkL = (__half*)(smem + 13056);
    __half* sA2H = (__half*)(smem + 17408);    // [128][136]
    __half* sA2L = (__half*)(smem + 52224);
    __half* sA3H = (__half*)(smem + 87040);    // [128][72]
    __half* sA3L = (__half*)(smem + 105472);
    float*  sScr = (float*)(smem + 123904);    // [16][256]
    float*  sH3  = (float*)(smem + 140288);    // [128][33]

    int tid = threadIdx.x;
    int w = tid >> 5, lane = tid & 31;
    int m0 = blockIdx.x * 128;
    int mr = w >> 1;
    int m0w = mr * 16;
    float* scr = sScr + w * 256;

    typedef wmma::fragment<wmma::matrix_a, 16,16,16, __half, wmma::col_major> FragAc;
    typedef wmma::fragment<wmma::matrix_a, 16,16,16, __half, wmma::row_major> FragAr;
    typedef wmma::fragment<wmma::matrix_b, 16,16,16, __half, wmma::row_major> FragB;
    typedef wmma::fragment<wmma::accumulator, 16,16,16, float> FragC;

    FragC acc[4];
    #pragma unroll
    for (int c = 0; c < 4; c++) wmma::fill_fragment(acc[c], 0.0f);
    int nb1 = (w & 1) * 4;

    #pragma unroll 1
    for (int t = 0; t < 13; t++) {
        __syncthreads();
        #pragma unroll
        for (int i = tid; i < 1024; i += 512) {
            int j = i >> 7, m = i & 127;
            size_t src = (size_t)(8 * t + j) * (size_t)B + (size_t)(m0 + m);
            __half2 vh = g_af2h[src];
            __half2 vl = g_af2l[src];
            sAkH[(2*j) * 136 + m]     = __low2half(vh);
            sAkH[(2*j + 1) * 136 + m] = __high2half(vh);
            sAkL[(2*j) * 136 + m]     = __low2half(vl);
            sAkL[(2*j + 1) * 136 + m] = __high2half(vl);
        }
        #pragma unroll
        for (int i = tid; i < 1024; i += 512) {
            int kk = i >> 6, c2 = i & 63;
            *(__half2*)&sBkH[kk * 136 + 2 * c2] =
                ((const __half2*)g_w1th)[(16 * t + kk) * 64 + c2];
            *(__half2*)&sBkL[kk * 136 + 2 * c2] =
                ((const __half2*)g_w1tl)[(16 * t + kk) * 64 + c2];
        }
        __syncthreads();

        FragAc ah, al;
        wmma::load_matrix_sync(ah, sAkH + m0w, 136);
        wmma::load_matrix_sync(al, sAkL + m0w, 136);
        #pragma unroll
        for (int c = 0; c < 4; c++) {
            int n0 = (nb1 + c) * 16;
            FragB bh, bl;
            wmma::load_matrix_sync(bh, sBkH + n0, 136);
            wmma::load_matrix_sync(bl, sBkL + n0, 136);
            wmma::mma_sync(acc[c], ah, bh, acc[c]);
            wmma::mma_sync(acc[c], ah, bl, acc[c]);
            wmma::mma_sync(acc[c], al, bh, acc[c]);
        }
    }
    #pragma unroll 1
    for (int c = 0; c < 4; c++) {
        __syncwarp();
        wmma::store_matrix_sync(scr, acc[c], 16, wmma::mem_row_major);
        __syncwarp();
        int n0 = (nb1 + c) * 16;
        #pragma unroll
        for (int i = 0; i < 8; i++) {
            int idx = i * 32 + lane;
            int r = idx >> 4, cc = idx & 15;
            int n = n0 + cc, m = m0w + r;
            float v = scr[idx] + __ldg(mlp_b1 + n);
            v = fmaxf(v, 0.f);
            __half hv = __float2half_rn(v);
            sA2H[m * 136 + n] = hv;
            sA2L[m * 136 + n] = __float2half_rn(v - __half2float(hv));
        }
    }
    __syncthreads();

    FragC acc2[2];
    #pragma unroll
    for (int c = 0; c < 2; c++) wmma::fill_fragment(acc2[c], 0.0f);
    int nb2 = (w & 1) * 2;

    #pragma unroll 1
    for (int t = 0; t < 8; t++) {
        __syncthreads();
        if (tid < 512) {
            int kk = tid >> 5, c2 = tid & 31;
            *(__half2*)&sBkH[kk * 136 + 2 * c2] =
                ((const __half2*)g_w2th)[(16 * t + kk) * 32 + c2];
            *(__half2*)&sBkL[kk * 136 + 2 * c2] =
                ((const __half2*)g_w2tl)[(16 * t + kk) * 32 + c2];
        }
        __syncthreads();

        FragAr ah, al;
        wmma::load_matrix_sync(ah, sA2H + m0w * 136 + 16 * t, 136);
        wmma::load_matrix_sync(al, sA2L + m0w * 136 + 16 * t, 136);
        #pragma unroll
        for (int c = 0; c < 2; c++) {
            int n0 = (nb2 + c) * 16;
            FragB bh, bl;
            wmma::load_matrix_sync(bh, sBkH + n0, 136);
            wmma::load_matrix_sync(bl, sBkL + n0, 136);
            wmma::mma_sync(acc2[c], ah, bh, acc2[c]);
            wmma::mma_sync(acc2[c], ah, bl, acc2[c]);
            wmma::mma_sync(acc2[c], al, bh, acc2[c]);
        }
    }
    #pragma unroll 1
    for (int c = 0; c < 2; c++) {
        __syncwarp();
        wmma::store_matrix_sync(scr, acc2[c], 16, wmma::mem_row_major);
        __syncwarp();
        int n0 = (nb2 + c) * 16;
        #pragma unroll
        for (int i = 0; i < 8; i++) {
            int idx = i * 32 + lane;
            int r = idx >> 4, cc = idx & 15;
            int n = n0 + cc, m = m0w + r;
            float v = scr[idx] + __ldg(mlp_b2 + n);
            v = fmaxf(v, 0.f);
            __half hv = __float2half_rn(v);
            sA3H[m * 72 + n] = hv;
            sA3L[m * 72 + n] = __float2half_rn(v - __half2float(hv));
        }
    }
    __syncthreads();

    FragC acc3;
    wmma::fill_fragment(acc3, 0.0f);
    int n03 = (w & 1) * 16;

    #pragma unroll 1
    for (int t = 0; t < 4; t++) {
        __syncthreads();
        if (tid < 256) {
            int kk = tid >> 4, c2 = tid & 15;
            *(__half2*)&sBkH[kk * 136 + 2 * c2] =
                ((const __half2*)g_w3th)[(16 * t + kk) * 16 + c2];
            *(__half2*)&sBkL[kk * 136 + 2 * c2] =
                ((const __half2*)g_w3tl)[(16 * t + kk) * 16 + c2];
        }
        __syncthreads();

        FragAr ah, al;
        wmma::load_matrix_sync(ah, sA3H + m0w * 72 + 16 * t, 72);
        wmma::load_matrix_sync(al, sA3L + m0w * 72 + 16 * t, 72);
        FragB bh, bl;
        wmma::load_matrix_sync(bh, sBkH + n03, 136);
        wmma::load_matrix_sync(bl, sBkL + n03, 136);
        wmma::mma_sync(acc3, ah, bh, acc3);
        wmma::mma_sync(acc3, ah, bl, acc3);
        wmma::mma_sync(acc3, al, bh, acc3);
    }
    __syncwarp();
    wmma::store_matrix_sync(scr, acc3, 16, wmma::mem_row_major);
    __syncwarp();
    #pragma unroll
    for (int i = 0; i < 8; i++) {
        int idx = i * 32 + lane;
        int r = idx >> 4, cc = idx & 15;
        int n = n03 + cc, m = m0w + r;
        float v = scr[idx] + __ldg(mlp_b3 + n);
        sH3[m * 33 + n] = fmaxf(v, 0.f);
    }
    __syncthreads();

    if (tid < 128) {
        int m = tid;
        float logit = __ldg(mlp_b4);
        #pragma unroll
        for (int o = 0; o < 32; o++)
            logit += __ldg(mlp_w4 + o) * sH3[m * 33 + o];
        out[m0 + m] = 1.f / (1.f + expf(-logit));
    }
}

// ---------------------------------------------------------------------------
extern "C" void kernel_launch(void* const* d_in, const int* in_sizes, int n_in,
                              void* d_out, int out_size)
{
    const int*   userid   = (const int*)d_in[0];
    const int*   itemid   = (const int*)d_in[1];
    const int*   user_age = (const int*)d_in[2];
    const int*   gender   = (const int*)d_in[3];
    const int*   user_occ = (const int*)d_in[4];
    const int*   item_kind= (const int*)d_in[5];
    const int*   his_id   = (const int*)d_in[6];
    const int*   his_kind = (const int*)d_in[7];
    const float* user_emb = (const float*)d_in[8];
    const float* item_emb = (const float*)d_in[9];
    const float* age_emb  = (const float*)d_in[10];
    const float* gen_emb  = (const float*)d_in[11];
    const float* occ_emb  = (const float*)d_in[12];
    const float* kind_emb = (const float*)d_in[13];
    const float* act_w1 = (const float*)d_in[14];
    const float* act_b1 = (const float*)d_in[15];
    const float* act_w2 = (const float*)d_in[16];
    const float* act_b2 = (const float*)d_in[17];
    const float* act_w3 = (const float*)d_in[18];
    const float* act_b3 = (const float*)d_in[19];
    const float* mlp_w1 = (const float*)d_in[20];
    const float* mlp_b1 = (const float*)d_in[21];
    const float* mlp_w2 = (const float*)d_in[22];
    const float* mlp_b2 = (const float*)d_in[23];
    const float* mlp_w3 = (const float*)d_in[24];
    const float* mlp_b3 = (const float*)d_in[25];
    const float* mlp_w4 = (const float*)d_in[26];
    const float* mlp_b4 = (const float*)d_in[27];

    int B = in_sizes[0];
    int nb = (B + 127) / 128;

    cudaFuncSetAttribute((const void*)t2_mlp,
                         cudaFuncAttributeMaxDynamicSharedMemorySize, T2_SMEM);

    prep_tables<<<196, 256>>>(act_w1, mlp_w1, mlp_w2, mlp_w3, kind_emb);

    k0_feat<<<nb, 128>>>(userid, itemid, user_age, gender, user_occ, item_kind,
                         user_emb, item_emb, age_emb, gen_emb, occ_emb, kind_emb,
                         act_b1, B);

    k1s_pool<<<nb, 128>>>(his_id, his_kind, item_emb, kind_emb, act_w1,
                          act_w2, act_b2, act_w3, act_b3, B);

    t2_mlp<<<nb, 512, T2_SMEM>>>(mlp_b1, mlp_b2, mlp_b3, mlp_w4, mlp_b4,
                                 (float*)d_out, B);
}